// round 1
// baseline (speedup 1.0000x reference)
#include <cuda_runtime.h>
#include <cuda_bf16.h>

#define N_NODES 40000
#define N_EDGES 640000
#define F 128
#define SCALE_INV 0.08838834764831845f   // 1/sqrt(128)

// ---- static scratch (no runtime allocation allowed) ----
__device__ float g_H[N_NODES * F];      // feat @ W_fc
__device__ float g_Q[N_NODES * F];      // feat @ Wq
__device__ float g_K[N_NODES * F];      // feat @ Wk
__device__ float g_ex[N_EDGES];         // exp(e) per edge
__device__ float g_denom[N_NODES];      // softmax denominator per dst

// ---------------------------------------------------------------------------
// Zero out + denom (out is poisoned 0xAA by the harness)
// ---------------------------------------------------------------------------
__global__ void zero_kernel(float* __restrict__ out) {
    int i = blockIdx.x * blockDim.x + threadIdx.x;
    if (i < N_NODES * F) out[i] = 0.0f;
    if (i < N_NODES)     g_denom[i] = 0.0f;
}

// ---------------------------------------------------------------------------
// Fused 3-way GEMM: H = feat@W_fc, Q = feat@Wq, K = feat@Wk
// blockIdx.y in {0,1,2} selects weight/output. Tile: 32 rows x 128 cols.
// 256 threads; each thread computes a 4x4 register block.
// ---------------------------------------------------------------------------
__global__ __launch_bounds__(256) void gemm3_kernel(
    const float* __restrict__ feat,
    const float* __restrict__ Wfc,
    const float* __restrict__ Wq,
    const float* __restrict__ Wk)
{
    __shared__ float As[32][F];   // 16 KB

    const float* W;
    float* O;
    if (blockIdx.y == 0)      { W = Wfc; O = g_H; }
    else if (blockIdx.y == 1) { W = Wq;  O = g_Q; }
    else                      { W = Wk;  O = g_K; }

    const int row0 = blockIdx.x * 32;
    const int tid  = threadIdx.x;

    // cooperative load of A tile: 32*128 floats = 1024 float4, 4 per thread
    {
        const float4* fsrc = (const float4*)(feat + (size_t)row0 * F);
        float4* adst = (float4*)(&As[0][0]);
#pragma unroll
        for (int j = 0; j < 4; j++)
            adst[tid + j * 256] = fsrc[tid + j * 256];
    }
    __syncthreads();

    const int ty4 = (tid >> 5) * 4;   // row group (0,4,...,28)
    const int tx4 = (tid & 31) * 4;   // col group (0,4,...,124)

    float acc[4][4];
#pragma unroll
    for (int r = 0; r < 4; r++)
#pragma unroll
        for (int c = 0; c < 4; c++) acc[r][c] = 0.0f;

#pragma unroll 8
    for (int k = 0; k < F; k++) {
        float4 b = __ldg((const float4*)(W + (k << 7) + tx4));
        float a0 = As[ty4 + 0][k];
        float a1 = As[ty4 + 1][k];
        float a2 = As[ty4 + 2][k];
        float a3 = As[ty4 + 3][k];
        acc[0][0] += a0 * b.x; acc[0][1] += a0 * b.y; acc[0][2] += a0 * b.z; acc[0][3] += a0 * b.w;
        acc[1][0] += a1 * b.x; acc[1][1] += a1 * b.y; acc[1][2] += a1 * b.z; acc[1][3] += a1 * b.w;
        acc[2][0] += a2 * b.x; acc[2][1] += a2 * b.y; acc[2][2] += a2 * b.z; acc[2][3] += a2 * b.w;
        acc[3][0] += a3 * b.x; acc[3][1] += a3 * b.y; acc[3][2] += a3 * b.z; acc[3][3] += a3 * b.w;
    }

#pragma unroll
    for (int r = 0; r < 4; r++) {
        float4 v = make_float4(acc[r][0], acc[r][1], acc[r][2], acc[r][3]);
        *(float4*)(O + (size_t)(row0 + ty4 + r) * F + tx4) = v;
    }
}

// ---------------------------------------------------------------------------
// Edge pass 1: one warp per edge.
//   ex = exp( dot(Q[dst], K[src]) / sqrt(F) );  denom[dst] += ex
// (segment-max skipped: e ~ N(0,1) here, exp cannot overflow; softmax is
//  mathematically identical with or without the max shift.)
// ---------------------------------------------------------------------------
__global__ __launch_bounds__(256) void edge_score_kernel(
    const int* __restrict__ src, const int* __restrict__ dst)
{
    int gw = (blockIdx.x * blockDim.x + threadIdx.x) >> 5;   // warp id = edge id
    if (gw >= N_EDGES) return;
    int lane = threadIdx.x & 31;

    int s = __ldg(&src[gw]);
    int d = __ldg(&dst[gw]);

    float4 q = *(const float4*)(g_Q + (size_t)d * F + lane * 4);
    float4 k = *(const float4*)(g_K + (size_t)s * F + lane * 4);
    float v = q.x * k.x + q.y * k.y + q.z * k.z + q.w * k.w;

    v += __shfl_xor_sync(0xFFFFFFFFu, v, 16);
    v += __shfl_xor_sync(0xFFFFFFFFu, v, 8);
    v += __shfl_xor_sync(0xFFFFFFFFu, v, 4);
    v += __shfl_xor_sync(0xFFFFFFFFu, v, 2);
    v += __shfl_xor_sync(0xFFFFFFFFu, v, 1);

    if (lane == 0) {
        float ex = __expf(v * SCALE_INV);
        g_ex[gw] = ex;
        atomicAdd(&g_denom[d], ex);
    }
}

// ---------------------------------------------------------------------------
// Edge pass 2: one warp per edge.
//   a = ex / denom[dst];  out[dst] += H[src] * a   (vector RED)
// ---------------------------------------------------------------------------
__global__ __launch_bounds__(256) void edge_aggregate_kernel(
    const int* __restrict__ src, const int* __restrict__ dst,
    float* __restrict__ out)
{
    int gw = (blockIdx.x * blockDim.x + threadIdx.x) >> 5;
    if (gw >= N_EDGES) return;
    int lane = threadIdx.x & 31;

    int s = __ldg(&src[gw]);
    int d = __ldg(&dst[gw]);

    float a = __ldg(&g_ex[gw]) / __ldg(&g_denom[d]);

    float4 h = *(const float4*)(g_H + (size_t)s * F + lane * 4);
    float x = h.x * a, y = h.y * a, z = h.z * a, w = h.w * a;

    float* p = out + (size_t)d * F + lane * 4;
    asm volatile("red.global.add.v4.f32 [%0], {%1, %2, %3, %4};"
                 :: "l"(p), "f"(x), "f"(y), "f"(z), "f"(w) : "memory");
}

// ---------------------------------------------------------------------------
// Inputs (metadata order): 0 feat, 1 loc, 2 W_fc, 3 Wq, 4 Wk, 5 Wq2, 6 Wk2,
// 7 G_w, 8 embed, 9 boundaries, 10 src, 11 dst, 12 inter_ids
// (loc/Wq2/Wk2/G_w/embed/boundaries/inter_ids feed the dead e2 branch.)
// ---------------------------------------------------------------------------
extern "C" void kernel_launch(void* const* d_in, const int* in_sizes, int n_in,
                              void* d_out, int out_size)
{
    const float* feat = (const float*)d_in[0];
    const float* Wfc  = (const float*)d_in[2];
    const float* Wq   = (const float*)d_in[3];
    const float* Wk   = (const float*)d_in[4];
    const int*   src  = (const int*)d_in[10];
    const int*   dst  = (const int*)d_in[11];
    float* out = (float*)d_out;

    // 1. zero out + denom
    {
        int total = N_NODES * F;
        zero_kernel<<<(total + 255) / 256, 256>>>(out);
    }

    // 2. H, Q, K GEMMs (N=40000 divisible by 32 -> 1250 row tiles)
    {
        dim3 grid(N_NODES / 32, 3);
        gemm3_kernel<<<grid, 256>>>(feat, Wfc, Wq, Wk);
    }

    // 3. edge scores + denominators (one warp per edge)
    {
        long long threads = (long long)N_EDGES * 32;
        int blocks = (int)((threads + 255) / 256);
        edge_score_kernel<<<blocks, 256>>>(src, dst);
    }

    // 4. weighted aggregation
    {
        long long threads = (long long)N_EDGES * 32;
        int blocks = (int)((threads + 255) / 256);
        edge_aggregate_kernel<<<blocks, 256>>>(src, dst, out);
    }
}

// round 2
// speedup vs baseline: 1.2104x; 1.2104x over previous
#include <cuda_runtime.h>
#include <cuda_bf16.h>
#include <cstdint>

#define N_NODES 40000
#define N_EDGES 640000
#define F 128
#define SCALE_INV 0.08838834764831845f   // 1/sqrt(128)

#define LDA 132   // A smem row stride (floats): 4-bank shift per row
#define LDB 136   // B smem row stride (floats): 8-bank shift per row
#define SMEM_BYTES ((64 * LDA + 128 * LDB) * 4)

// ---- static scratch (no runtime allocation allowed) ----
__device__ float g_H[N_NODES * F];      // feat @ W_fc
__device__ float g_Q[N_NODES * F];      // feat @ Wq
__device__ float g_K[N_NODES * F];      // feat @ Wk
__device__ float g_ex[N_EDGES];         // exp(e) per edge
__device__ float g_denom[N_NODES];      // softmax denominator per dst

// ---------------------------------------------------------------------------
// Zero out + denom (out is poisoned 0xAA by the harness)
// ---------------------------------------------------------------------------
__global__ void zero_kernel(float* __restrict__ out) {
    int i = blockIdx.x * blockDim.x + threadIdx.x;
    if (i < N_NODES * F) out[i] = 0.0f;
    if (i < N_NODES)     g_denom[i] = 0.0f;
}

__device__ __forceinline__ uint32_t f2tf32(float x) {
    uint32_t r;
    asm("cvt.rna.tf32.f32 %0, %1;" : "=r"(r) : "f"(x));
    return r;
}

// ---------------------------------------------------------------------------
// Fused 3-way GEMM on tensor cores (tf32 mma.sync, fp32 accumulate):
//   H = feat@W_fc, Q = feat@Wq, K = feat@Wk   (blockIdx.y selects)
// Block tile: 64 rows x 128 cols, K=128. 256 threads = 8 warps
// (4 m-groups x 2 n-groups). Warp tile: 16x64 via 8x mma.m16n8k8 per k-step.
// A tile (64x128) and the full weight (128x128) staged in dynamic smem.
// ---------------------------------------------------------------------------
__global__ __launch_bounds__(256) void gemm3_tf32_kernel(
    const float* __restrict__ feat,
    const float* __restrict__ Wfc,
    const float* __restrict__ Wq,
    const float* __restrict__ Wk)
{
    extern __shared__ float sm[];
    float* As = sm;               // [64][LDA]
    float* Bs = sm + 64 * LDA;    // [128][LDB]

    const float* W;
    float* O;
    if (blockIdx.y == 0)      { W = Wfc; O = g_H; }
    else if (blockIdx.y == 1) { W = Wq;  O = g_Q; }
    else                      { W = Wk;  O = g_K; }

    const int tid  = threadIdx.x;
    const int row0 = blockIdx.x * 64;

    // stage A tile: 64x128 = 2048 float4 (8 per thread)
    for (int i = tid; i < 2048; i += 256) {
        int r = i >> 5, c4 = (i & 31) << 2;
        *(float4*)(As + r * LDA + c4) =
            *(const float4*)(feat + (size_t)(row0 + r) * F + c4);
    }
    // stage W: 128x128 = 4096 float4 (16 per thread)
    for (int i = tid; i < 4096; i += 256) {
        int r = i >> 5, c4 = (i & 31) << 2;
        *(float4*)(Bs + r * LDB + c4) =
            *(const float4*)(W + r * F + c4);
    }
    __syncthreads();

    const int wid  = tid >> 5;
    const int lane = tid & 31;
    const int wm   = (wid & 3) << 4;    // 0,16,32,48
    const int wn   = (wid >> 2) << 6;   // 0,64
    const int grp  = lane >> 2;         // 0..7
    const int qid  = lane & 3;          // 0..3

    float acc[8][4];
#pragma unroll
    for (int t = 0; t < 8; t++)
#pragma unroll
        for (int j = 0; j < 4; j++) acc[t][j] = 0.0f;

#pragma unroll
    for (int ks = 0; ks < 16; ks++) {
        const int k0 = ks << 3;
        // A fragment (m16 k8, row-major)
        uint32_t a0 = f2tf32(As[(wm + grp)     * LDA + k0 + qid]);
        uint32_t a1 = f2tf32(As[(wm + grp + 8) * LDA + k0 + qid]);
        uint32_t a2 = f2tf32(As[(wm + grp)     * LDA + k0 + qid + 4]);
        uint32_t a3 = f2tf32(As[(wm + grp + 8) * LDA + k0 + qid + 4]);
#pragma unroll
        for (int nt = 0; nt < 8; nt++) {
            const int n0 = wn + (nt << 3);
            // B fragment (k8 n8, col-major view of W[k][n])
            uint32_t b0 = f2tf32(Bs[(k0 + qid)     * LDB + n0 + grp]);
            uint32_t b1 = f2tf32(Bs[(k0 + qid + 4) * LDB + n0 + grp]);
            asm volatile(
                "mma.sync.aligned.m16n8k8.row.col.f32.tf32.tf32.f32 "
                "{%0,%1,%2,%3}, {%4,%5,%6,%7}, {%8,%9}, {%0,%1,%2,%3};"
                : "+f"(acc[nt][0]), "+f"(acc[nt][1]),
                  "+f"(acc[nt][2]), "+f"(acc[nt][3])
                : "r"(a0), "r"(a1), "r"(a2), "r"(a3), "r"(b0), "r"(b1));
        }
    }

    // store: c0,c1 at (row, col..col+1); c2,c3 at (row+8, col..col+1)
    const int r = row0 + wm + grp;
#pragma unroll
    for (int nt = 0; nt < 8; nt++) {
        const int col = wn + (nt << 3) + (qid << 1);
        *(float2*)(O + (size_t)r * F + col)       = make_float2(acc[nt][0], acc[nt][1]);
        *(float2*)(O + (size_t)(r + 8) * F + col) = make_float2(acc[nt][2], acc[nt][3]);
    }
}

// ---------------------------------------------------------------------------
// Edge pass 1: one warp per edge.
//   ex = exp( dot(Q[dst], K[src]) / sqrt(F) );  denom[dst] += ex
// (segment-max skipped: e ~ N(0,1), exp cannot overflow; softmax identical.)
// ---------------------------------------------------------------------------
__global__ __launch_bounds__(256) void edge_score_kernel(
    const int* __restrict__ src, const int* __restrict__ dst)
{
    int gw = (blockIdx.x * blockDim.x + threadIdx.x) >> 5;   // warp id = edge id
    if (gw >= N_EDGES) return;
    int lane = threadIdx.x & 31;

    int s = __ldg(&src[gw]);
    int d = __ldg(&dst[gw]);

    float4 q = *(const float4*)(g_Q + (size_t)d * F + lane * 4);
    float4 k = *(const float4*)(g_K + (size_t)s * F + lane * 4);
    float v = q.x * k.x + q.y * k.y + q.z * k.z + q.w * k.w;

    v += __shfl_xor_sync(0xFFFFFFFFu, v, 16);
    v += __shfl_xor_sync(0xFFFFFFFFu, v, 8);
    v += __shfl_xor_sync(0xFFFFFFFFu, v, 4);
    v += __shfl_xor_sync(0xFFFFFFFFu, v, 2);
    v += __shfl_xor_sync(0xFFFFFFFFu, v, 1);

    if (lane == 0) {
        float ex = __expf(v * SCALE_INV);
        g_ex[gw] = ex;
        atomicAdd(&g_denom[d], ex);
    }
}

// ---------------------------------------------------------------------------
// Edge pass 2: one warp per edge.
//   a = ex / denom[dst];  out[dst] += H[src] * a   (vector RED)
// ---------------------------------------------------------------------------
__global__ __launch_bounds__(256) void edge_aggregate_kernel(
    const int* __restrict__ src, const int* __restrict__ dst,
    float* __restrict__ out)
{
    int gw = (blockIdx.x * blockDim.x + threadIdx.x) >> 5;
    if (gw >= N_EDGES) return;
    int lane = threadIdx.x & 31;

    int s = __ldg(&src[gw]);
    int d = __ldg(&dst[gw]);

    float a = __ldg(&g_ex[gw]) / __ldg(&g_denom[d]);

    float4 h = *(const float4*)(g_H + (size_t)s * F + lane * 4);
    float x = h.x * a, y = h.y * a, z = h.z * a, w = h.w * a;

    float* p = out + (size_t)d * F + lane * 4;
    asm volatile("red.global.add.v4.f32 [%0], {%1, %2, %3, %4};"
                 :: "l"(p), "f"(x), "f"(y), "f"(z), "f"(w) : "memory");
}

// ---------------------------------------------------------------------------
// Inputs (metadata order): 0 feat, 1 loc, 2 W_fc, 3 Wq, 4 Wk, 5 Wq2, 6 Wk2,
// 7 G_w, 8 embed, 9 boundaries, 10 src, 11 dst, 12 inter_ids
// (loc/Wq2/Wk2/G_w/embed/boundaries/inter_ids feed the dead e2 branch.)
// ---------------------------------------------------------------------------
extern "C" void kernel_launch(void* const* d_in, const int* in_sizes, int n_in,
                              void* d_out, int out_size)
{
    const float* feat = (const float*)d_in[0];
    const float* Wfc  = (const float*)d_in[2];
    const float* Wq   = (const float*)d_in[3];
    const float* Wk   = (const float*)d_in[4];
    const int*   src  = (const int*)d_in[10];
    const int*   dst  = (const int*)d_in[11];
    float* out = (float*)d_out;

    static bool attr_set = false;
    if (!attr_set) {
        cudaFuncSetAttribute(gemm3_tf32_kernel,
                             cudaFuncAttributeMaxDynamicSharedMemorySize,
                             SMEM_BYTES);
        attr_set = true;
    }

    // 1. zero out + denom
    {
        int total = N_NODES * F;
        zero_kernel<<<(total + 255) / 256, 256>>>(out);
    }

    // 2. H, Q, K GEMMs on tensor cores (40000 / 64 = 625 row tiles)
    {
        dim3 grid(N_NODES / 64, 3);
        gemm3_tf32_kernel<<<grid, 256, SMEM_BYTES>>>(feat, Wfc, Wq, Wk);
    }

    // 3. edge scores + denominators (one warp per edge)
    {
        long long threads = (long long)N_EDGES * 32;
        int blocks = (int)((threads + 255) / 256);
        edge_score_kernel<<<blocks, 256>>>(src, dst);
    }

    // 4. weighted aggregation
    {
        long long threads = (long long)N_EDGES * 32;
        int blocks = (int)((threads + 255) / 256);
        edge_aggregate_kernel<<<blocks, 256>>>(src, dst, out);
    }
}

// round 3
// speedup vs baseline: 2.0286x; 1.6760x over previous
#include <cuda_runtime.h>
#include <cuda_bf16.h>
#include <cstdint>

#define N_NODES 40000
#define N_EDGES 640000
#define F 128
#define SCALE_INV 0.08838834764831845f   // 1/sqrt(128)

#define NBLK 157            // ceil(40000/256) scan blocks

#define LDA 132
#define LDB 136
#define SMEM_BYTES ((64 * LDA + 128 * LDB) * 4)

// ---- static scratch ----
__device__ float g_H[N_NODES * F];
__device__ float g_Q[N_NODES * F];
__device__ float g_K[N_NODES * F];
__device__ int   g_deg[N_NODES];
__device__ int   g_rowStart[N_NODES + 1];
__device__ int   g_cursor[N_NODES];
__device__ int   g_srcSorted[N_EDGES];
__device__ int   g_bsum[NBLK];

// ---------------------------------------------------------------------------
__global__ void init_kernel() {
    int i = blockIdx.x * blockDim.x + threadIdx.x;
    if (i < N_NODES) g_deg[i] = 0;
}

__global__ void hist_kernel(const int* __restrict__ dst) {
    int i = blockIdx.x * blockDim.x + threadIdx.x;
    if (i < N_EDGES) atomicAdd(&g_deg[__ldg(&dst[i])], 1);
}

// block-local exclusive scan of deg -> rowStart(local), block totals -> g_bsum
__global__ __launch_bounds__(256) void scan1_kernel() {
    __shared__ int s[256];
    int tid = threadIdx.x;
    int i = blockIdx.x * 256 + tid;
    int v = (i < N_NODES) ? g_deg[i] : 0;
    s[tid] = v;
    __syncthreads();
#pragma unroll
    for (int off = 1; off < 256; off <<= 1) {
        int t = (tid >= off) ? s[tid - off] : 0;
        __syncthreads();
        s[tid] += t;
        __syncthreads();
    }
    if (i < N_NODES) g_rowStart[i] = s[tid] - v;   // exclusive
    if (tid == 255) g_bsum[blockIdx.x] = s[255];
}

// single-block exclusive scan of the NBLK block sums (in place)
__global__ __launch_bounds__(256) void scan2_kernel() {
    __shared__ int s[256];
    int tid = threadIdx.x;
    int v = (tid < NBLK) ? g_bsum[tid] : 0;
    s[tid] = v;
    __syncthreads();
#pragma unroll
    for (int off = 1; off < 256; off <<= 1) {
        int t = (tid >= off) ? s[tid - off] : 0;
        __syncthreads();
        s[tid] += t;
        __syncthreads();
    }
    if (tid < NBLK) g_bsum[tid] = s[tid] - v;      // exclusive
}

// add block offsets; copy to cursor; set sentinel
__global__ void scan3_kernel() {
    int i = blockIdx.x * blockDim.x + threadIdx.x;
    if (i < N_NODES) {
        int r = g_rowStart[i] + g_bsum[i >> 8];
        g_rowStart[i] = r;
        g_cursor[i] = r;
    }
    if (i == 0) g_rowStart[N_NODES] = N_EDGES;
}

__global__ void scatter_kernel(const int* __restrict__ src,
                               const int* __restrict__ dst) {
    int e = blockIdx.x * blockDim.x + threadIdx.x;
    if (e < N_EDGES) {
        int d = __ldg(&dst[e]);
        int slot = atomicAdd(&g_cursor[d], 1);
        g_srcSorted[slot] = __ldg(&src[e]);
    }
}

// ---------------------------------------------------------------------------
__device__ __forceinline__ uint32_t f2tf32(float x) {
    uint32_t r;
    asm("cvt.rna.tf32.f32 %0, %1;" : "=r"(r) : "f"(x));
    return r;
}

// Fused 3-way GEMM on tensor cores (tf32): H/Q/K = feat @ {Wfc,Wq,Wk}
__global__ __launch_bounds__(256) void gemm3_tf32_kernel(
    const float* __restrict__ feat,
    const float* __restrict__ Wfc,
    const float* __restrict__ Wq,
    const float* __restrict__ Wk)
{
    extern __shared__ float sm[];
    float* As = sm;               // [64][LDA]
    float* Bs = sm + 64 * LDA;    // [128][LDB]

    const float* W;
    float* O;
    if (blockIdx.y == 0)      { W = Wfc; O = g_H; }
    else if (blockIdx.y == 1) { W = Wq;  O = g_Q; }
    else                      { W = Wk;  O = g_K; }

    const int tid  = threadIdx.x;
    const int row0 = blockIdx.x * 64;

    for (int i = tid; i < 2048; i += 256) {
        int r = i >> 5, c4 = (i & 31) << 2;
        *(float4*)(As + r * LDA + c4) =
            *(const float4*)(feat + (size_t)(row0 + r) * F + c4);
    }
    for (int i = tid; i < 4096; i += 256) {
        int r = i >> 5, c4 = (i & 31) << 2;
        *(float4*)(Bs + r * LDB + c4) =
            *(const float4*)(W + r * F + c4);
    }
    __syncthreads();

    const int wid  = tid >> 5;
    const int lane = tid & 31;
    const int wm   = (wid & 3) << 4;
    const int wn   = (wid >> 2) << 6;
    const int grp  = lane >> 2;
    const int qid  = lane & 3;

    float acc[8][4];
#pragma unroll
    for (int t = 0; t < 8; t++)
#pragma unroll
        for (int j = 0; j < 4; j++) acc[t][j] = 0.0f;

#pragma unroll
    for (int ks = 0; ks < 16; ks++) {
        const int k0 = ks << 3;
        uint32_t a0 = f2tf32(As[(wm + grp)     * LDA + k0 + qid]);
        uint32_t a1 = f2tf32(As[(wm + grp + 8) * LDA + k0 + qid]);
        uint32_t a2 = f2tf32(As[(wm + grp)     * LDA + k0 + qid + 4]);
        uint32_t a3 = f2tf32(As[(wm + grp + 8) * LDA + k0 + qid + 4]);
#pragma unroll
        for (int nt = 0; nt < 8; nt++) {
            const int n0 = wn + (nt << 3);
            uint32_t b0 = f2tf32(Bs[(k0 + qid)     * LDB + n0 + grp]);
            uint32_t b1 = f2tf32(Bs[(k0 + qid + 4) * LDB + n0 + grp]);
            asm volatile(
                "mma.sync.aligned.m16n8k8.row.col.f32.tf32.tf32.f32 "
                "{%0,%1,%2,%3}, {%4,%5,%6,%7}, {%8,%9}, {%0,%1,%2,%3};"
                : "+f"(acc[nt][0]), "+f"(acc[nt][1]),
                  "+f"(acc[nt][2]), "+f"(acc[nt][3])
                : "r"(a0), "r"(a1), "r"(a2), "r"(a3), "r"(b0), "r"(b1));
        }
    }

    const int r = row0 + wm + grp;
#pragma unroll
    for (int nt = 0; nt < 8; nt++) {
        const int col = wn + (nt << 3) + (qid << 1);
        *(float2*)(O + (size_t)r * F + col)       = make_float2(acc[nt][0], acc[nt][1]);
        *(float2*)(O + (size_t)(r + 8) * F + col) = make_float2(acc[nt][2], acc[nt][3]);
    }
}

// ---------------------------------------------------------------------------
// Fused attention: one warp per dst node. Q[d] in registers; loop incoming
// edges: dot(Q,K[s]) -> ex; acc += ex*H[s]; den += ex. out = acc/den.
// (No max-shift needed: e ~ N(0,1), exp cannot overflow; identical softmax.)
// ---------------------------------------------------------------------------
__global__ __launch_bounds__(256) void fused_attn_kernel(float* __restrict__ out)
{
    int gw = (blockIdx.x * blockDim.x + threadIdx.x) >> 5;   // node id
    if (gw >= N_NODES) return;
    int lane = threadIdx.x & 31;

    int beg = g_rowStart[gw];
    int end = g_rowStart[gw + 1];

    float* orow = out + (size_t)gw * F + lane * 4;
    if (beg == end) {                       // no incoming edges -> zeros
        *(float4*)orow = make_float4(0.f, 0.f, 0.f, 0.f);
        return;
    }

    float4 q = *(const float4*)(g_Q + (size_t)gw * F + lane * 4);

    float ax = 0.f, ay = 0.f, az = 0.f, aw = 0.f;
    float den = 0.f;

    for (int chunk = beg; chunk < end; chunk += 32) {
        int idx = chunk + lane;
        int myS = (idx < end) ? __ldg(&g_srcSorted[idx]) : 0;
        int m = end - chunk; if (m > 32) m = 32;

        int j = 0;
        for (; j + 2 <= m; j += 2) {
            int s0 = __shfl_sync(0xFFFFFFFFu, myS, j);
            int s1 = __shfl_sync(0xFFFFFFFFu, myS, j + 1);
            float4 k0 = *(const float4*)(g_K + (size_t)s0 * F + lane * 4);
            float4 k1 = *(const float4*)(g_K + (size_t)s1 * F + lane * 4);
            float4 h0 = *(const float4*)(g_H + (size_t)s0 * F + lane * 4);
            float4 h1 = *(const float4*)(g_H + (size_t)s1 * F + lane * 4);

            float v0 = q.x * k0.x + q.y * k0.y + q.z * k0.z + q.w * k0.w;
            float v1 = q.x * k1.x + q.y * k1.y + q.z * k1.z + q.w * k1.w;
#pragma unroll
            for (int o = 16; o > 0; o >>= 1) {
                v0 += __shfl_xor_sync(0xFFFFFFFFu, v0, o);
                v1 += __shfl_xor_sync(0xFFFFFFFFu, v1, o);
            }
            float e0 = __expf(v0 * SCALE_INV);
            float e1 = __expf(v1 * SCALE_INV);
            den += e0 + e1;
            ax += e0 * h0.x + e1 * h1.x;
            ay += e0 * h0.y + e1 * h1.y;
            az += e0 * h0.z + e1 * h1.z;
            aw += e0 * h0.w + e1 * h1.w;
        }
        if (j < m) {
            int s0 = __shfl_sync(0xFFFFFFFFu, myS, j);
            float4 k0 = *(const float4*)(g_K + (size_t)s0 * F + lane * 4);
            float4 h0 = *(const float4*)(g_H + (size_t)s0 * F + lane * 4);
            float v0 = q.x * k0.x + q.y * k0.y + q.z * k0.z + q.w * k0.w;
#pragma unroll
            for (int o = 16; o > 0; o >>= 1)
                v0 += __shfl_xor_sync(0xFFFFFFFFu, v0, o);
            float e0 = __expf(v0 * SCALE_INV);
            den += e0;
            ax += e0 * h0.x; ay += e0 * h0.y; az += e0 * h0.z; aw += e0 * h0.w;
        }
    }

    float inv = 1.0f / den;
    *(float4*)orow = make_float4(ax * inv, ay * inv, az * inv, aw * inv);
}

// ---------------------------------------------------------------------------
// Inputs: 0 feat, 1 loc, 2 W_fc, 3 Wq, 4 Wk, 5 Wq2, 6 Wk2, 7 G_w, 8 embed,
// 9 boundaries, 10 src, 11 dst, 12 inter_ids  (e2 branch is dead code)
// ---------------------------------------------------------------------------
extern "C" void kernel_launch(void* const* d_in, const int* in_sizes, int n_in,
                              void* d_out, int out_size)
{
    const float* feat = (const float*)d_in[0];
    const float* Wfc  = (const float*)d_in[2];
    const float* Wq   = (const float*)d_in[3];
    const float* Wk   = (const float*)d_in[4];
    const int*   src  = (const int*)d_in[10];
    const int*   dst  = (const int*)d_in[11];
    float* out = (float*)d_out;

    static bool attr_set = false;
    if (!attr_set) {
        cudaFuncSetAttribute(gemm3_tf32_kernel,
                             cudaFuncAttributeMaxDynamicSharedMemorySize,
                             SMEM_BYTES);
        attr_set = true;
    }

    // CSR build
    init_kernel<<<(N_NODES + 255) / 256, 256>>>();
    hist_kernel<<<(N_EDGES + 255) / 256, 256>>>(dst);
    scan1_kernel<<<NBLK, 256>>>();
    scan2_kernel<<<1, 256>>>();
    scan3_kernel<<<(N_NODES + 255) / 256, 256>>>();
    scatter_kernel<<<(N_EDGES + 255) / 256, 256>>>(src, dst);

    // H, Q, K GEMMs (overlap-independent of CSR, same stream serializes)
    {
        dim3 grid(N_NODES / 64, 3);
        gemm3_tf32_kernel<<<grid, 256, SMEM_BYTES>>>(feat, Wfc, Wq, Wk);
    }

    // fused score + softmax + aggregate: one warp per node
    {
        int warps = N_NODES;
        int blocks = (warps * 32 + 255) / 256;
        fused_attn_kernel<<<blocks, 256>>>(out);
    }
}

// round 4
// speedup vs baseline: 2.2452x; 1.1068x over previous
#include <cuda_runtime.h>
#include <cuda_fp16.h>
#include <cstdint>

#define N_NODES 40000
#define N_EDGES 640000
#define F 128
#define SCALE_INV 0.08838834764831845f   // 1/sqrt(128)

#define NBLK 157            // ceil(40000/256) scan blocks

#define LDA 132
#define LDB 136
#define SMEM_BYTES ((128 * LDA + 128 * LDB) * 4)   // 137216 B

// ---- static scratch ----
__device__ __half g_Hh[N_NODES * F];    // feat @ W_fc   (fp16)
__device__ float  g_Q [N_NODES * F];    // feat @ Wq     (fp32)
__device__ __half g_Kh[N_NODES * F];    // feat @ Wk     (fp16)
__device__ int    g_deg[N_NODES];
__device__ int    g_rowStart[N_NODES + 1];
__device__ int    g_cursor[N_NODES];
__device__ int    g_srcSorted[N_EDGES];
__device__ int    g_bsum[NBLK];

// ---------------------------------------------------------------------------
__global__ void init_kernel() {
    int i = blockIdx.x * blockDim.x + threadIdx.x;
    if (i < N_NODES) g_deg[i] = 0;
}

__global__ void hist_kernel(const int* __restrict__ dst) {
    int i = blockIdx.x * blockDim.x + threadIdx.x;
    if (i < N_EDGES) atomicAdd(&g_deg[__ldg(&dst[i])], 1);
}

// block-local exclusive scan of deg -> rowStart(local), block totals -> g_bsum
__global__ __launch_bounds__(256) void scan1_kernel() {
    __shared__ int s[256];
    int tid = threadIdx.x;
    int i = blockIdx.x * 256 + tid;
    int v = (i < N_NODES) ? g_deg[i] : 0;
    s[tid] = v;
    __syncthreads();
#pragma unroll
    for (int off = 1; off < 256; off <<= 1) {
        int t = (tid >= off) ? s[tid - off] : 0;
        __syncthreads();
        s[tid] += t;
        __syncthreads();
    }
    if (i < N_NODES) g_rowStart[i] = s[tid] - v;   // exclusive (block-local)
    if (tid == 255) g_bsum[blockIdx.x] = s[255];
}

// add block offsets (each block reduces bsum[t < blockIdx] itself);
// copy to cursor; set sentinel.
__global__ __launch_bounds__(256) void scan23_kernel() {
    __shared__ int red[256];
    int tid = threadIdx.x;
    int v = (tid < NBLK && tid < blockIdx.x) ? g_bsum[tid] : 0;
    red[tid] = v;
    __syncthreads();
#pragma unroll
    for (int off = 128; off > 0; off >>= 1) {
        if (tid < off) red[tid] += red[tid + off];
        __syncthreads();
    }
    int offset = red[0];

    int i = blockIdx.x * 256 + tid;
    if (i < N_NODES) {
        int r = g_rowStart[i] + offset;
        g_rowStart[i] = r;
        g_cursor[i] = r;
    }
    if (i == 0) g_rowStart[N_NODES] = N_EDGES;
}

__global__ void scatter_kernel(const int* __restrict__ src,
                               const int* __restrict__ dst) {
    int e = blockIdx.x * blockDim.x + threadIdx.x;
    if (e < N_EDGES) {
        int d = __ldg(&dst[e]);
        int slot = atomicAdd(&g_cursor[d], 1);
        g_srcSorted[slot] = __ldg(&src[e]);
    }
}

// ---------------------------------------------------------------------------
__device__ __forceinline__ uint32_t f2tf32(float x) {
    uint32_t r;
    asm("cvt.rna.tf32.f32 %0, %1;" : "=r"(r) : "f"(x));
    return r;
}

// ---------------------------------------------------------------------------
// Fused 3-way GEMM (tf32 tensor cores): one 128x128 row tile per CTA;
// A staged ONCE, the three weights staged sequentially into Bs.
// H (fp16), Q (fp32), K (fp16) written per weight.
// 256 threads = 8 warps (4m x 2n); warp tile 32x64 (2 m-frags x 8 n-tiles).
// ---------------------------------------------------------------------------
__global__ __launch_bounds__(256) void gemm3_tf32_kernel(
    const float* __restrict__ feat,
    const float* __restrict__ Wfc,
    const float* __restrict__ Wq,
    const float* __restrict__ Wk)
{
    extern __shared__ float sm[];
    float* As = sm;                 // [128][LDA]
    float* Bs = sm + 128 * LDA;     // [128][LDB]

    const int tid  = threadIdx.x;
    const int row0 = blockIdx.x * 128;

    // stage A tile: 128x128 = 4096 float4 (16 per thread), guard tail rows
    for (int i = tid; i < 4096; i += 256) {
        int r = i >> 5, c4 = (i & 31) << 2;
        float4 v = make_float4(0.f, 0.f, 0.f, 0.f);
        if (row0 + r < N_NODES)
            v = *(const float4*)(feat + (size_t)(row0 + r) * F + c4);
        *(float4*)(As + r * LDA + c4) = v;
    }

    const int wid  = tid >> 5;
    const int lane = tid & 31;
    const int wm   = (wid & 3) << 5;    // 0,32,64,96
    const int wn   = (wid >> 2) << 6;   // 0,64
    const int grp  = lane >> 2;         // 0..7
    const int qid  = lane & 3;          // 0..3

    const float* Ws[3] = { Wfc, Wq, Wk };

#pragma unroll
    for (int j = 0; j < 3; j++) {
        __syncthreads();   // A ready (j==0) / previous k-loop done with Bs
        const float* W = Ws[j];
        for (int i = tid; i < 4096; i += 256) {
            int r = i >> 5, c4 = (i & 31) << 2;
            *(float4*)(Bs + r * LDB + c4) = *(const float4*)(W + r * F + c4);
        }
        __syncthreads();

        float acc[2][8][4];
#pragma unroll
        for (int mi = 0; mi < 2; mi++)
#pragma unroll
            for (int nt = 0; nt < 8; nt++)
#pragma unroll
                for (int c = 0; c < 4; c++) acc[mi][nt][c] = 0.0f;

#pragma unroll
        for (int ks = 0; ks < 16; ks++) {
            const int k0 = ks << 3;
            uint32_t a[2][4];
#pragma unroll
            for (int mi = 0; mi < 2; mi++) {
                const int rb = wm + (mi << 4);
                a[mi][0] = f2tf32(As[(rb + grp)     * LDA + k0 + qid]);
                a[mi][1] = f2tf32(As[(rb + grp + 8) * LDA + k0 + qid]);
                a[mi][2] = f2tf32(As[(rb + grp)     * LDA + k0 + qid + 4]);
                a[mi][3] = f2tf32(As[(rb + grp + 8) * LDA + k0 + qid + 4]);
            }
#pragma unroll
            for (int nt = 0; nt < 8; nt++) {
                const int n0 = wn + (nt << 3);
                uint32_t b0 = f2tf32(Bs[(k0 + qid)     * LDB + n0 + grp]);
                uint32_t b1 = f2tf32(Bs[(k0 + qid + 4) * LDB + n0 + grp]);
#pragma unroll
                for (int mi = 0; mi < 2; mi++) {
                    asm volatile(
                        "mma.sync.aligned.m16n8k8.row.col.f32.tf32.tf32.f32 "
                        "{%0,%1,%2,%3}, {%4,%5,%6,%7}, {%8,%9}, {%0,%1,%2,%3};"
                        : "+f"(acc[mi][nt][0]), "+f"(acc[mi][nt][1]),
                          "+f"(acc[mi][nt][2]), "+f"(acc[mi][nt][3])
                        : "r"(a[mi][0]), "r"(a[mi][1]), "r"(a[mi][2]),
                          "r"(a[mi][3]), "r"(b0), "r"(b1));
                }
            }
        }

        // epilogue
#pragma unroll
        for (int mi = 0; mi < 2; mi++) {
            const int r = row0 + wm + (mi << 4) + grp;   // and r+8
#pragma unroll
            for (int nt = 0; nt < 8; nt++) {
                const int col = wn + (nt << 3) + (qid << 1);
                if (j == 1) {        // Q fp32
                    if (r < N_NODES)
                        *(float2*)(g_Q + (size_t)r * F + col) =
                            make_float2(acc[mi][nt][0], acc[mi][nt][1]);
                    if (r + 8 < N_NODES)
                        *(float2*)(g_Q + (size_t)(r + 8) * F + col) =
                            make_float2(acc[mi][nt][2], acc[mi][nt][3]);
                } else {             // H (j==0) / K (j==2) fp16
                    __half* O = (j == 0) ? g_Hh : g_Kh;
                    if (r < N_NODES)
                        *(__half2*)(O + (size_t)r * F + col) =
                            __floats2half2_rn(acc[mi][nt][0], acc[mi][nt][1]);
                    if (r + 8 < N_NODES)
                        *(__half2*)(O + (size_t)(r + 8) * F + col) =
                            __floats2half2_rn(acc[mi][nt][2], acc[mi][nt][3]);
                }
            }
        }
    }
}

// ---------------------------------------------------------------------------
// Fused attention: one warp per dst node. Q[d] (fp32) in registers; loop
// incoming edges: dot(Q, K[s]) -> ex; acc += ex*H[s]; den += ex; out=acc/den.
// K/H gathered as fp16 (half the edge traffic), math in fp32.
// ---------------------------------------------------------------------------
__device__ __forceinline__ void load_h4(const __half* base, size_t off,
                                        float& x, float& y, float& z, float& w) {
    uint2 raw = *(const uint2*)(base + off);
    __half2 p0 = *(__half2*)&raw.x;
    __half2 p1 = *(__half2*)&raw.y;
    float2 f0 = __half22float2(p0);
    float2 f1 = __half22float2(p1);
    x = f0.x; y = f0.y; z = f1.x; w = f1.y;
}

__global__ __launch_bounds__(256) void fused_attn_kernel(float* __restrict__ out)
{
    int gw = (blockIdx.x * blockDim.x + threadIdx.x) >> 5;   // node id
    if (gw >= N_NODES) return;
    int lane = threadIdx.x & 31;

    int beg = g_rowStart[gw];
    int end = g_rowStart[gw + 1];

    float* orow = out + (size_t)gw * F + lane * 4;
    if (beg == end) {                       // no incoming edges -> zeros
        *(float4*)orow = make_float4(0.f, 0.f, 0.f, 0.f);
        return;
    }

    float4 q = *(const float4*)(g_Q + (size_t)gw * F + lane * 4);

    float ax = 0.f, ay = 0.f, az = 0.f, aw = 0.f;
    float den = 0.f;

    for (int chunk = beg; chunk < end; chunk += 32) {
        int idx = chunk + lane;
        int myS = (idx < end) ? __ldg(&g_srcSorted[idx]) : 0;
        int m = end - chunk; if (m > 32) m = 32;

        int j = 0;
        for (; j + 2 <= m; j += 2) {
            int s0 = __shfl_sync(0xFFFFFFFFu, myS, j);
            int s1 = __shfl_sync(0xFFFFFFFFu, myS, j + 1);
            size_t o0 = (size_t)s0 * F + lane * 4;
            size_t o1 = (size_t)s1 * F + lane * 4;
            float k0x,k0y,k0z,k0w, k1x,k1y,k1z,k1w;
            float h0x,h0y,h0z,h0w, h1x,h1y,h1z,h1w;
            load_h4(g_Kh, o0, k0x,k0y,k0z,k0w);
            load_h4(g_Kh, o1, k1x,k1y,k1z,k1w);
            load_h4(g_Hh, o0, h0x,h0y,h0z,h0w);
            load_h4(g_Hh, o1, h1x,h1y,h1z,h1w);

            float v0 = q.x * k0x + q.y * k0y + q.z * k0z + q.w * k0w;
            float v1 = q.x * k1x + q.y * k1y + q.z * k1z + q.w * k1w;
#pragma unroll
            for (int o = 16; o > 0; o >>= 1) {
                v0 += __shfl_xor_sync(0xFFFFFFFFu, v0, o);
                v1 += __shfl_xor_sync(0xFFFFFFFFu, v1, o);
            }
            float e0 = __expf(v0 * SCALE_INV);
            float e1 = __expf(v1 * SCALE_INV);
            den += e0 + e1;
            ax += e0 * h0x + e1 * h1x;
            ay += e0 * h0y + e1 * h1y;
            az += e0 * h0z + e1 * h1z;
            aw += e0 * h0w + e1 * h1w;
        }
        if (j < m) {
            int s0 = __shfl_sync(0xFFFFFFFFu, myS, j);
            size_t o0 = (size_t)s0 * F + lane * 4;
            float kx,ky,kz,kw, hx,hy,hz,hw;
            load_h4(g_Kh, o0, kx,ky,kz,kw);
            load_h4(g_Hh, o0, hx,hy,hz,hw);
            float v0 = q.x * kx + q.y * ky + q.z * kz + q.w * kw;
#pragma unroll
            for (int o = 16; o > 0; o >>= 1)
                v0 += __shfl_xor_sync(0xFFFFFFFFu, v0, o);
            float e0 = __expf(v0 * SCALE_INV);
            den += e0;
            ax += e0 * hx; ay += e0 * hy; az += e0 * hz; aw += e0 * hw;
        }
    }

    float inv = 1.0f / den;
    *(float4*)orow = make_float4(ax * inv, ay * inv, az * inv, aw * inv);
}

// ---------------------------------------------------------------------------
// Inputs: 0 feat, 1 loc, 2 W_fc, 3 Wq, 4 Wk, 5 Wq2, 6 Wk2, 7 G_w, 8 embed,
// 9 boundaries, 10 src, 11 dst, 12 inter_ids  (e2 branch is dead code)
// ---------------------------------------------------------------------------
extern "C" void kernel_launch(void* const* d_in, const int* in_sizes, int n_in,
                              void* d_out, int out_size)
{
    const float* feat = (const float*)d_in[0];
    const float* Wfc  = (const float*)d_in[2];
    const float* Wq   = (const float*)d_in[3];
    const float* Wk   = (const float*)d_in[4];
    const int*   src  = (const int*)d_in[10];
    const int*   dst  = (const int*)d_in[11];
    float* out = (float*)d_out;

    static bool attr_set = false;
    if (!attr_set) {
        cudaFuncSetAttribute(gemm3_tf32_kernel,
                             cudaFuncAttributeMaxDynamicSharedMemorySize,
                             SMEM_BYTES);
        attr_set = true;
    }

    // CSR build
    init_kernel<<<(N_NODES + 255) / 256, 256>>>();
    hist_kernel<<<(N_EDGES + 255) / 256, 256>>>(dst);
    scan1_kernel<<<NBLK, 256>>>();
    scan23_kernel<<<NBLK, 256>>>();
    scatter_kernel<<<(N_EDGES + 255) / 256, 256>>>(src, dst);

    // H, Q, K GEMMs: 313 tiles of 128 rows, all three weights per CTA
    gemm3_tf32_kernel<<<(N_NODES + 127) / 128, 256, SMEM_BYTES>>>(
        feat, Wfc, Wq, Wk);

    // fused score + softmax + aggregate: one warp per node
    fused_attn_kernel<<<(N_NODES * 32 + 255) / 256, 256>>>(out);
}

// round 5
// speedup vs baseline: 2.4511x; 1.0917x over previous
#include <cuda_runtime.h>
#include <cuda_fp16.h>
#include <cstdint>

#define N_NODES 40000
#define N_EDGES 640000
#define F 128
#define SCALE_INV 0.08838834764831845f   // 1/sqrt(128)

#define NBLK 157            // ceil(40000/256) scan blocks

#define LDA 132
#define LDB 136
#define SMEM_BYTES ((128 * LDA + 128 * LDB) * 4)   // 137216 B

// ---- static scratch (module-load zero-initialized; g_deg kept zero across
//      invocations by scan1's zero-after-read) ----
__device__ __half g_Hh[N_NODES * F];    // feat @ W_fc   (fp16)
__device__ float  g_Q [N_NODES * F];    // feat @ Wq     (fp32)
__device__ __half g_Kh[N_NODES * F];    // feat @ Wk     (fp16)
__device__ int    g_deg[N_NODES];
__device__ int    g_rowStart[N_NODES + 1];
__device__ int    g_cursor[N_NODES];
__device__ int    g_srcSorted[N_EDGES];
__device__ int    g_bsum[NBLK];

// ---------------------------------------------------------------------------
__global__ void hist_kernel(const int* __restrict__ dst) {
    int i = blockIdx.x * blockDim.x + threadIdx.x;   // 4 edges per thread
    int base = i << 2;
    if (base + 3 < N_EDGES) {
        int4 d = *(const int4*)(dst + base);
        atomicAdd(&g_deg[d.x], 1);
        atomicAdd(&g_deg[d.y], 1);
        atomicAdd(&g_deg[d.z], 1);
        atomicAdd(&g_deg[d.w], 1);
    } else {
        for (int e = base; e < N_EDGES; e++)
            atomicAdd(&g_deg[__ldg(&dst[e])], 1);
    }
}

// block-local exclusive scan of deg -> rowStart(local), block totals -> bsum.
// Zeroes g_deg after reading (keeps the invariant for the next invocation).
__global__ __launch_bounds__(256) void scan1_kernel() {
    __shared__ int s[256];
    int tid = threadIdx.x;
    int i = blockIdx.x * 256 + tid;
    int v = 0;
    if (i < N_NODES) { v = g_deg[i]; g_deg[i] = 0; }
    s[tid] = v;
    __syncthreads();
#pragma unroll
    for (int off = 1; off < 256; off <<= 1) {
        int t = (tid >= off) ? s[tid - off] : 0;
        __syncthreads();
        s[tid] += t;
        __syncthreads();
    }
    if (i < N_NODES) g_rowStart[i] = s[tid] - v;   // exclusive (block-local)
    if (tid == 255) g_bsum[blockIdx.x] = s[255];
}

// add block offsets (each block reduces bsum[t < blockIdx] itself);
// copy to cursor; set sentinel.
__global__ __launch_bounds__(256) void scan23_kernel() {
    __shared__ int red[256];
    int tid = threadIdx.x;
    int v = (tid < NBLK && tid < blockIdx.x) ? g_bsum[tid] : 0;
    red[tid] = v;
    __syncthreads();
#pragma unroll
    for (int off = 128; off > 0; off >>= 1) {
        if (tid < off) red[tid] += red[tid + off];
        __syncthreads();
    }
    int offset = red[0];

    int i = blockIdx.x * 256 + tid;
    if (i < N_NODES) {
        int r = g_rowStart[i] + offset;
        g_rowStart[i] = r;
        g_cursor[i] = r;
    }
    if (i == 0) g_rowStart[N_NODES] = N_EDGES;
}

__global__ void scatter_kernel(const int* __restrict__ src,
                               const int* __restrict__ dst) {
    int i = blockIdx.x * blockDim.x + threadIdx.x;   // 4 edges per thread
    int base = i << 2;
    if (base + 3 < N_EDGES) {
        int4 d = *(const int4*)(dst + base);
        int4 s = *(const int4*)(src + base);
        g_srcSorted[atomicAdd(&g_cursor[d.x], 1)] = s.x;
        g_srcSorted[atomicAdd(&g_cursor[d.y], 1)] = s.y;
        g_srcSorted[atomicAdd(&g_cursor[d.z], 1)] = s.z;
        g_srcSorted[atomicAdd(&g_cursor[d.w], 1)] = s.w;
    } else {
        for (int e = base; e < N_EDGES; e++) {
            int d = __ldg(&dst[e]);
            g_srcSorted[atomicAdd(&g_cursor[d], 1)] = __ldg(&src[e]);
        }
    }
}

// ---------------------------------------------------------------------------
__device__ __forceinline__ uint32_t f2tf32(float x) {
    uint32_t r;
    asm("cvt.rna.tf32.f32 %0, %1;" : "=r"(r) : "f"(x));
    return r;
}

// Fused 3-way GEMM (tf32 tensor cores): one 128x128 row tile per CTA;
// A staged ONCE, the three weights staged sequentially into Bs.
__global__ __launch_bounds__(256) void gemm3_tf32_kernel(
    const float* __restrict__ feat,
    const float* __restrict__ Wfc,
    const float* __restrict__ Wq,
    const float* __restrict__ Wk)
{
    extern __shared__ float sm[];
    float* As = sm;                 // [128][LDA]
    float* Bs = sm + 128 * LDA;     // [128][LDB]

    const int tid  = threadIdx.x;
    const int row0 = blockIdx.x * 128;

    for (int i = tid; i < 4096; i += 256) {
        int r = i >> 5, c4 = (i & 31) << 2;
        float4 v = make_float4(0.f, 0.f, 0.f, 0.f);
        if (row0 + r < N_NODES)
            v = *(const float4*)(feat + (size_t)(row0 + r) * F + c4);
        *(float4*)(As + r * LDA + c4) = v;
    }

    const int wid  = tid >> 5;
    const int lane = tid & 31;
    const int wm   = (wid & 3) << 5;
    const int wn   = (wid >> 2) << 6;
    const int grp  = lane >> 2;
    const int qid  = lane & 3;

    const float* Ws[3] = { Wfc, Wq, Wk };

#pragma unroll
    for (int j = 0; j < 3; j++) {
        __syncthreads();
        const float* W = Ws[j];
        for (int i = tid; i < 4096; i += 256) {
            int r = i >> 5, c4 = (i & 31) << 2;
            *(float4*)(Bs + r * LDB + c4) = *(const float4*)(W + r * F + c4);
        }
        __syncthreads();

        float acc[2][8][4];
#pragma unroll
        for (int mi = 0; mi < 2; mi++)
#pragma unroll
            for (int nt = 0; nt < 8; nt++)
#pragma unroll
                for (int c = 0; c < 4; c++) acc[mi][nt][c] = 0.0f;

#pragma unroll
        for (int ks = 0; ks < 16; ks++) {
            const int k0 = ks << 3;
            uint32_t a[2][4];
#pragma unroll
            for (int mi = 0; mi < 2; mi++) {
                const int rb = wm + (mi << 4);
                a[mi][0] = f2tf32(As[(rb + grp)     * LDA + k0 + qid]);
                a[mi][1] = f2tf32(As[(rb + grp + 8) * LDA + k0 + qid]);
                a[mi][2] = f2tf32(As[(rb + grp)     * LDA + k0 + qid + 4]);
                a[mi][3] = f2tf32(As[(rb + grp + 8) * LDA + k0 + qid + 4]);
            }
#pragma unroll
            for (int nt = 0; nt < 8; nt++) {
                const int n0 = wn + (nt << 3);
                uint32_t b0 = f2tf32(Bs[(k0 + qid)     * LDB + n0 + grp]);
                uint32_t b1 = f2tf32(Bs[(k0 + qid + 4) * LDB + n0 + grp]);
#pragma unroll
                for (int mi = 0; mi < 2; mi++) {
                    asm volatile(
                        "mma.sync.aligned.m16n8k8.row.col.f32.tf32.tf32.f32 "
                        "{%0,%1,%2,%3}, {%4,%5,%6,%7}, {%8,%9}, {%0,%1,%2,%3};"
                        : "+f"(acc[mi][nt][0]), "+f"(acc[mi][nt][1]),
                          "+f"(acc[mi][nt][2]), "+f"(acc[mi][nt][3])
                        : "r"(a[mi][0]), "r"(a[mi][1]), "r"(a[mi][2]),
                          "r"(a[mi][3]), "r"(b0), "r"(b1));
                }
            }
        }

#pragma unroll
        for (int mi = 0; mi < 2; mi++) {
            const int r = row0 + wm + (mi << 4) + grp;
#pragma unroll
            for (int nt = 0; nt < 8; nt++) {
                const int col = wn + (nt << 3) + (qid << 1);
                if (j == 1) {
                    if (r < N_NODES)
                        *(float2*)(g_Q + (size_t)r * F + col) =
                            make_float2(acc[mi][nt][0], acc[mi][nt][1]);
                    if (r + 8 < N_NODES)
                        *(float2*)(g_Q + (size_t)(r + 8) * F + col) =
                            make_float2(acc[mi][nt][2], acc[mi][nt][3]);
                } else {
                    __half* O = (j == 0) ? g_Hh : g_Kh;
                    if (r < N_NODES)
                        *(__half2*)(O + (size_t)r * F + col) =
                            __floats2half2_rn(acc[mi][nt][0], acc[mi][nt][1]);
                    if (r + 8 < N_NODES)
                        *(__half2*)(O + (size_t)(r + 8) * F + col) =
                            __floats2half2_rn(acc[mi][nt][2], acc[mi][nt][3]);
                }
            }
        }
    }
}

// ---------------------------------------------------------------------------
// Fused attention, ILP-4 edge loop: one warp per dst node.
// ---------------------------------------------------------------------------
__device__ __forceinline__ void load_h4(const __half* base, size_t off,
                                        float& x, float& y, float& z, float& w) {
    uint2 raw = *(const uint2*)(base + off);
    __half2 p0 = *(__half2*)&raw.x;
    __half2 p1 = *(__half2*)&raw.y;
    float2 f0 = __half22float2(p0);
    float2 f1 = __half22float2(p1);
    x = f0.x; y = f0.y; z = f1.x; w = f1.y;
}

__global__ __launch_bounds__(256) void fused_attn_kernel(float* __restrict__ out)
{
    int gw = (blockIdx.x * blockDim.x + threadIdx.x) >> 5;   // node id
    if (gw >= N_NODES) return;
    int lane = threadIdx.x & 31;

    int beg = g_rowStart[gw];
    int end = g_rowStart[gw + 1];

    float* orow = out + (size_t)gw * F + lane * 4;
    if (beg == end) {
        *(float4*)orow = make_float4(0.f, 0.f, 0.f, 0.f);
        return;
    }

    float4 q = *(const float4*)(g_Q + (size_t)gw * F + lane * 4);

    float ax = 0.f, ay = 0.f, az = 0.f, aw = 0.f;
    float den = 0.f;

    for (int chunk = beg; chunk < end; chunk += 32) {
        int idx = chunk + lane;
        int myS = (idx < end) ? __ldg(&g_srcSorted[idx]) : 0;
        int m = end - chunk; if (m > 32) m = 32;

        int j = 0;
        for (; j + 4 <= m; j += 4) {
            int s0 = __shfl_sync(0xFFFFFFFFu, myS, j);
            int s1 = __shfl_sync(0xFFFFFFFFu, myS, j + 1);
            int s2 = __shfl_sync(0xFFFFFFFFu, myS, j + 2);
            int s3 = __shfl_sync(0xFFFFFFFFu, myS, j + 3);
            size_t o0 = (size_t)s0 * F + lane * 4;
            size_t o1 = (size_t)s1 * F + lane * 4;
            size_t o2 = (size_t)s2 * F + lane * 4;
            size_t o3 = (size_t)s3 * F + lane * 4;
            float k0x,k0y,k0z,k0w, k1x,k1y,k1z,k1w;
            float k2x,k2y,k2z,k2w, k3x,k3y,k3z,k3w;
            float h0x,h0y,h0z,h0w, h1x,h1y,h1z,h1w;
            float h2x,h2y,h2z,h2w, h3x,h3y,h3z,h3w;
            load_h4(g_Kh, o0, k0x,k0y,k0z,k0w);
            load_h4(g_Kh, o1, k1x,k1y,k1z,k1w);
            load_h4(g_Kh, o2, k2x,k2y,k2z,k2w);
            load_h4(g_Kh, o3, k3x,k3y,k3z,k3w);
            load_h4(g_Hh, o0, h0x,h0y,h0z,h0w);
            load_h4(g_Hh, o1, h1x,h1y,h1z,h1w);
            load_h4(g_Hh, o2, h2x,h2y,h2z,h2w);
            load_h4(g_Hh, o3, h3x,h3y,h3z,h3w);

            float v0 = q.x*k0x + q.y*k0y + q.z*k0z + q.w*k0w;
            float v1 = q.x*k1x + q.y*k1y + q.z*k1z + q.w*k1w;
            float v2 = q.x*k2x + q.y*k2y + q.z*k2z + q.w*k2w;
            float v3 = q.x*k3x + q.y*k3y + q.z*k3z + q.w*k3w;
#pragma unroll
            for (int o = 16; o > 0; o >>= 1) {
                v0 += __shfl_xor_sync(0xFFFFFFFFu, v0, o);
                v1 += __shfl_xor_sync(0xFFFFFFFFu, v1, o);
                v2 += __shfl_xor_sync(0xFFFFFFFFu, v2, o);
                v3 += __shfl_xor_sync(0xFFFFFFFFu, v3, o);
            }
            float e0 = __expf(v0 * SCALE_INV);
            float e1 = __expf(v1 * SCALE_INV);
            float e2 = __expf(v2 * SCALE_INV);
            float e3 = __expf(v3 * SCALE_INV);
            den += (e0 + e1) + (e2 + e3);
            ax += e0*h0x + e1*h1x + e2*h2x + e3*h3x;
            ay += e0*h0y + e1*h1y + e2*h2y + e3*h3y;
            az += e0*h0z + e1*h1z + e2*h2z + e3*h3z;
            aw += e0*h0w + e1*h1w + e2*h2w + e3*h3w;
        }
        for (; j < m; j++) {
            int s0 = __shfl_sync(0xFFFFFFFFu, myS, j);
            size_t o0 = (size_t)s0 * F + lane * 4;
            float kx,ky,kz,kw, hx,hy,hz,hw;
            load_h4(g_Kh, o0, kx,ky,kz,kw);
            load_h4(g_Hh, o0, hx,hy,hz,hw);
            float v0 = q.x*kx + q.y*ky + q.z*kz + q.w*kw;
#pragma unroll
            for (int o = 16; o > 0; o >>= 1)
                v0 += __shfl_xor_sync(0xFFFFFFFFu, v0, o);
            float e0 = __expf(v0 * SCALE_INV);
            den += e0;
            ax += e0*hx; ay += e0*hy; az += e0*hz; aw += e0*hw;
        }
    }

    float inv = 1.0f / den;
    *(float4*)orow = make_float4(ax * inv, ay * inv, az * inv, aw * inv);
}

// ---------------------------------------------------------------------------
// Inputs: 0 feat, 1 loc, 2 W_fc, 3 Wq, 4 Wk, 5 Wq2, 6 Wk2, 7 G_w, 8 embed,
// 9 boundaries, 10 src, 11 dst, 12 inter_ids  (e2 branch is dead code)
// ---------------------------------------------------------------------------
extern "C" void kernel_launch(void* const* d_in, const int* in_sizes, int n_in,
                              void* d_out, int out_size)
{
    const float* feat = (const float*)d_in[0];
    const float* Wfc  = (const float*)d_in[2];
    const float* Wq   = (const float*)d_in[3];
    const float* Wk   = (const float*)d_in[4];
    const int*   src  = (const int*)d_in[10];
    const int*   dst  = (const int*)d_in[11];
    float* out = (float*)d_out;

    static cudaStream_t s2 = nullptr;
    static cudaEvent_t evFork = nullptr, evJoin = nullptr;
    if (!s2) {
        cudaFuncSetAttribute(gemm3_tf32_kernel,
                             cudaFuncAttributeMaxDynamicSharedMemorySize,
                             SMEM_BYTES);
        cudaStreamCreateWithFlags(&s2, cudaStreamNonBlocking);
        cudaEventCreateWithFlags(&evFork, cudaEventDisableTiming);
        cudaEventCreateWithFlags(&evJoin, cudaEventDisableTiming);
    }

    // fork: CSR build on s2, GEMM on the main (capture) stream
    cudaEventRecord(evFork, 0);
    cudaStreamWaitEvent(s2, evFork, 0);

    {   // --- s2: CSR build ---
        int t4 = (N_EDGES + 3) / 4;
        hist_kernel<<<(t4 + 255) / 256, 256, 0, s2>>>(dst);
        scan1_kernel<<<NBLK, 256, 0, s2>>>();
        scan23_kernel<<<NBLK, 256, 0, s2>>>();
        scatter_kernel<<<(t4 + 255) / 256, 256, 0, s2>>>(src, dst);
        cudaEventRecord(evJoin, s2);
    }

    // --- main stream: H, Q, K GEMMs ---
    gemm3_tf32_kernel<<<(N_NODES + 127) / 128, 256, SMEM_BYTES>>>(
        feat, Wfc, Wq, Wk);

    // join, then fused attention
    cudaStreamWaitEvent(0, evJoin, 0);
    fused_attn_kernel<<<(N_NODES * 32 + 255) / 256, 256>>>(out);
}

// round 6
// speedup vs baseline: 2.5637x; 1.0459x over previous
#include <cuda_runtime.h>
#include <cuda_fp16.h>
#include <cstdint>

#define N_NODES 40000
#define N_EDGES 640000
#define F 128
#define SCALE_INV 0.08838834764831845f   // 1/sqrt(128)

#define NBLK 157            // ceil(40000/256) scan blocks

#define LDA 132
#define LDB 136
#define SMEM_BYTES ((128 * LDA + 128 * LDB) * 4)   // 137216 B

// ---- static scratch ----
// Interleaved K/H (fp16): per node, 32 groups of 8 halves:
//   [g*8+0..3] = K cols 4g..4g+3,  [g*8+4..7] = H cols 4g..4g+3
__device__ __half g_KH[N_NODES * 2 * F];
__device__ float  g_Q [N_NODES * F];     // feat @ Wq (fp32)
__device__ int    g_deg[N_NODES];        // stays zero between invocations
__device__ int    g_rowStart[N_NODES + 1];
__device__ int    g_cursor[N_NODES];
__device__ int    g_srcSorted[N_EDGES];
__device__ int    g_bsum[NBLK];

// ---------------------------------------------------------------------------
__global__ void hist_kernel(const int* __restrict__ dst) {
    int base = (blockIdx.x * blockDim.x + threadIdx.x) << 3;   // 8 edges/thread
    if (base + 7 < N_EDGES) {
        int4 d0 = *(const int4*)(dst + base);
        int4 d1 = *(const int4*)(dst + base + 4);
        atomicAdd(&g_deg[d0.x], 1); atomicAdd(&g_deg[d0.y], 1);
        atomicAdd(&g_deg[d0.z], 1); atomicAdd(&g_deg[d0.w], 1);
        atomicAdd(&g_deg[d1.x], 1); atomicAdd(&g_deg[d1.y], 1);
        atomicAdd(&g_deg[d1.z], 1); atomicAdd(&g_deg[d1.w], 1);
    } else {
        for (int e = base; e < N_EDGES; e++)
            atomicAdd(&g_deg[__ldg(&dst[e])], 1);
    }
}

// block-local exclusive scan of deg -> rowStart(local), block totals -> bsum.
// Zeroes g_deg after reading (invariant for next invocation).
__global__ __launch_bounds__(256) void scan1_kernel() {
    __shared__ int s[256];
    int tid = threadIdx.x;
    int i = blockIdx.x * 256 + tid;
    int v = 0;
    if (i < N_NODES) { v = g_deg[i]; g_deg[i] = 0; }
    s[tid] = v;
    __syncthreads();
#pragma unroll
    for (int off = 1; off < 256; off <<= 1) {
        int t = (tid >= off) ? s[tid - off] : 0;
        __syncthreads();
        s[tid] += t;
        __syncthreads();
    }
    if (i < N_NODES) g_rowStart[i] = s[tid] - v;
    if (tid == 255) g_bsum[blockIdx.x] = s[255];
}

// add block offsets (each block reduces bsum[t < blockIdx] itself);
// copy to cursor; set sentinel.
__global__ __launch_bounds__(256) void scan23_kernel() {
    __shared__ int red[256];
    int tid = threadIdx.x;
    int v = (tid < NBLK && tid < blockIdx.x) ? g_bsum[tid] : 0;
    red[tid] = v;
    __syncthreads();
#pragma unroll
    for (int off = 128; off > 0; off >>= 1) {
        if (tid < off) red[tid] += red[tid + off];
        __syncthreads();
    }
    int offset = red[0];

    int i = blockIdx.x * 256 + tid;
    if (i < N_NODES) {
        int r = g_rowStart[i] + offset;
        g_rowStart[i] = r;
        g_cursor[i] = r;
    }
    if (i == 0) g_rowStart[N_NODES] = N_EDGES;
}

__global__ void scatter_kernel(const int* __restrict__ src,
                               const int* __restrict__ dst) {
    int base = (blockIdx.x * blockDim.x + threadIdx.x) << 3;   // 8 edges/thread
    if (base + 7 < N_EDGES) {
        int4 d0 = *(const int4*)(dst + base);
        int4 s0 = *(const int4*)(src + base);
        int4 d1 = *(const int4*)(dst + base + 4);
        int4 s1 = *(const int4*)(src + base + 4);
        int a0 = atomicAdd(&g_cursor[d0.x], 1);
        int a1 = atomicAdd(&g_cursor[d0.y], 1);
        int a2 = atomicAdd(&g_cursor[d0.z], 1);
        int a3 = atomicAdd(&g_cursor[d0.w], 1);
        int a4 = atomicAdd(&g_cursor[d1.x], 1);
        int a5 = atomicAdd(&g_cursor[d1.y], 1);
        int a6 = atomicAdd(&g_cursor[d1.z], 1);
        int a7 = atomicAdd(&g_cursor[d1.w], 1);
        g_srcSorted[a0] = s0.x; g_srcSorted[a1] = s0.y;
        g_srcSorted[a2] = s0.z; g_srcSorted[a3] = s0.w;
        g_srcSorted[a4] = s1.x; g_srcSorted[a5] = s1.y;
        g_srcSorted[a6] = s1.z; g_srcSorted[a7] = s1.w;
    } else {
        for (int e = base; e < N_EDGES; e++) {
            int d = __ldg(&dst[e]);
            g_srcSorted[atomicAdd(&g_cursor[d], 1)] = __ldg(&src[e]);
        }
    }
}

// ---------------------------------------------------------------------------
__device__ __forceinline__ uint32_t f2tf32(float x) {
    uint32_t r;
    asm("cvt.rna.tf32.f32 %0, %1;" : "=r"(r) : "f"(x));
    return r;
}

// Fused 3-way GEMM (tf32 tensor cores): one 128x128 row tile per CTA;
// A staged ONCE, the three weights staged sequentially into Bs.
// H (j=0) and K (j=2) write fp16 into the interleaved g_KH; Q (j=1) fp32.
__global__ __launch_bounds__(256) void gemm3_tf32_kernel(
    const float* __restrict__ feat,
    const float* __restrict__ Wfc,
    const float* __restrict__ Wq,
    const float* __restrict__ Wk)
{
    extern __shared__ float sm[];
    float* As = sm;                 // [128][LDA]
    float* Bs = sm + 128 * LDA;     // [128][LDB]

    const int tid  = threadIdx.x;
    const int row0 = blockIdx.x * 128;

    for (int i = tid; i < 4096; i += 256) {
        int r = i >> 5, c4 = (i & 31) << 2;
        float4 v = make_float4(0.f, 0.f, 0.f, 0.f);
        if (row0 + r < N_NODES)
            v = *(const float4*)(feat + (size_t)(row0 + r) * F + c4);
        *(float4*)(As + r * LDA + c4) = v;
    }

    const int wid  = tid >> 5;
    const int lane = tid & 31;
    const int wm   = (wid & 3) << 5;
    const int wn   = (wid >> 2) << 6;
    const int grp  = lane >> 2;
    const int qid  = lane & 3;

    const float* Ws[3] = { Wfc, Wq, Wk };

#pragma unroll
    for (int j = 0; j < 3; j++) {
        __syncthreads();
        const float* W = Ws[j];
        for (int i = tid; i < 4096; i += 256) {
            int r = i >> 5, c4 = (i & 31) << 2;
            *(float4*)(Bs + r * LDB + c4) = *(const float4*)(W + r * F + c4);
        }
        __syncthreads();

        float acc[2][8][4];
#pragma unroll
        for (int mi = 0; mi < 2; mi++)
#pragma unroll
            for (int nt = 0; nt < 8; nt++)
#pragma unroll
                for (int c = 0; c < 4; c++) acc[mi][nt][c] = 0.0f;

#pragma unroll
        for (int ks = 0; ks < 16; ks++) {
            const int k0 = ks << 3;
            uint32_t a[2][4];
#pragma unroll
            for (int mi = 0; mi < 2; mi++) {
                const int rb = wm + (mi << 4);
                a[mi][0] = f2tf32(As[(rb + grp)     * LDA + k0 + qid]);
                a[mi][1] = f2tf32(As[(rb + grp + 8) * LDA + k0 + qid]);
                a[mi][2] = f2tf32(As[(rb + grp)     * LDA + k0 + qid + 4]);
                a[mi][3] = f2tf32(As[(rb + grp + 8) * LDA + k0 + qid + 4]);
            }
#pragma unroll
            for (int nt = 0; nt < 8; nt++) {
                const int n0 = wn + (nt << 3);
                uint32_t b0 = f2tf32(Bs[(k0 + qid)     * LDB + n0 + grp]);
                uint32_t b1 = f2tf32(Bs[(k0 + qid + 4) * LDB + n0 + grp]);
#pragma unroll
                for (int mi = 0; mi < 2; mi++) {
                    asm volatile(
                        "mma.sync.aligned.m16n8k8.row.col.f32.tf32.tf32.f32 "
                        "{%0,%1,%2,%3}, {%4,%5,%6,%7}, {%8,%9}, {%0,%1,%2,%3};"
                        : "+f"(acc[mi][nt][0]), "+f"(acc[mi][nt][1]),
                          "+f"(acc[mi][nt][2]), "+f"(acc[mi][nt][3])
                        : "r"(a[mi][0]), "r"(a[mi][1]), "r"(a[mi][2]),
                          "r"(a[mi][3]), "r"(b0), "r"(b1));
                }
            }
        }

        const int khOff = (j == 0) ? 4 : 0;   // H -> slot+4, K -> slot+0
#pragma unroll
        for (int mi = 0; mi < 2; mi++) {
            const int r = row0 + wm + (mi << 4) + grp;
#pragma unroll
            for (int nt = 0; nt < 8; nt++) {
                const int col = wn + (nt << 3) + (qid << 1);   // col even
                if (j == 1) {          // Q fp32
                    if (r < N_NODES)
                        *(float2*)(g_Q + (size_t)r * F + col) =
                            make_float2(acc[mi][nt][0], acc[mi][nt][1]);
                    if (r + 8 < N_NODES)
                        *(float2*)(g_Q + (size_t)(r + 8) * F + col) =
                            make_float2(acc[mi][nt][2], acc[mi][nt][3]);
                } else {               // H/K fp16 interleaved
                    const int slot = ((col >> 2) << 3) + khOff + (col & 3);
                    if (r < N_NODES)
                        *(__half2*)(g_KH + (size_t)r * 256 + slot) =
                            __floats2half2_rn(acc[mi][nt][0], acc[mi][nt][1]);
                    if (r + 8 < N_NODES)
                        *(__half2*)(g_KH + (size_t)(r + 8) * 256 + slot) =
                            __floats2half2_rn(acc[mi][nt][2], acc[mi][nt][3]);
                }
            }
        }
    }
}

// ---------------------------------------------------------------------------
// Fused attention, ILP-4: one warp per dst node. One LDG.128 per edge-lane
// fetches 4 K-halves + 4 H-halves. 32-bit offsets throughout.
// ---------------------------------------------------------------------------
__device__ __forceinline__ void load_kh(unsigned off,
    float& kx, float& ky, float& kz, float& kw,
    float& hx, float& hy, float& hz, float& hw)
{
    uint4 raw = *(const uint4*)(g_KH + off);
    float2 f0 = __half22float2(*(__half2*)&raw.x);
    float2 f1 = __half22float2(*(__half2*)&raw.y);
    float2 f2 = __half22float2(*(__half2*)&raw.z);
    float2 f3 = __half22float2(*(__half2*)&raw.w);
    kx = f0.x; ky = f0.y; kz = f1.x; kw = f1.y;
    hx = f2.x; hy = f2.y; hz = f3.x; hw = f3.y;
}

__global__ __launch_bounds__(256) void fused_attn_kernel(float* __restrict__ out)
{
    int gw = (blockIdx.x * blockDim.x + threadIdx.x) >> 5;   // node id
    if (gw >= N_NODES) return;
    int lane = threadIdx.x & 31;

    int beg = g_rowStart[gw];
    int end = g_rowStart[gw + 1];

    float* orow = out + (size_t)gw * F + lane * 4;
    if (beg == end) {
        *(float4*)orow = make_float4(0.f, 0.f, 0.f, 0.f);
        return;
    }

    float4 q = *(const float4*)(g_Q + (unsigned)(gw * F + lane * 4));

    float ax = 0.f, ay = 0.f, az = 0.f, aw = 0.f;
    float den = 0.f;
    const unsigned lo = (unsigned)(lane << 3);

    for (int chunk = beg; chunk < end; chunk += 32) {
        int idx = chunk + lane;
        int myS = (idx < end) ? __ldg(&g_srcSorted[idx]) : 0;
        int m = end - chunk; if (m > 32) m = 32;

        int j = 0;
        for (; j + 4 <= m; j += 4) {
            unsigned o0 = (unsigned)__shfl_sync(0xFFFFFFFFu, myS, j)     * 256u + lo;
            unsigned o1 = (unsigned)__shfl_sync(0xFFFFFFFFu, myS, j + 1) * 256u + lo;
            unsigned o2 = (unsigned)__shfl_sync(0xFFFFFFFFu, myS, j + 2) * 256u + lo;
            unsigned o3 = (unsigned)__shfl_sync(0xFFFFFFFFu, myS, j + 3) * 256u + lo;
            float k0x,k0y,k0z,k0w, h0x,h0y,h0z,h0w;
            float k1x,k1y,k1z,k1w, h1x,h1y,h1z,h1w;
            float k2x,k2y,k2z,k2w, h2x,h2y,h2z,h2w;
            float k3x,k3y,k3z,k3w, h3x,h3y,h3z,h3w;
            load_kh(o0, k0x,k0y,k0z,k0w, h0x,h0y,h0z,h0w);
            load_kh(o1, k1x,k1y,k1z,k1w, h1x,h1y,h1z,h1w);
            load_kh(o2, k2x,k2y,k2z,k2w, h2x,h2y,h2z,h2w);
            load_kh(o3, k3x,k3y,k3z,k3w, h3x,h3y,h3z,h3w);

            float v0 = q.x*k0x + q.y*k0y + q.z*k0z + q.w*k0w;
            float v1 = q.x*k1x + q.y*k1y + q.z*k1z + q.w*k1w;
            float v2 = q.x*k2x + q.y*k2y + q.z*k2z + q.w*k2w;
            float v3 = q.x*k3x + q.y*k3y + q.z*k3z + q.w*k3w;
#pragma unroll
            for (int o = 16; o > 0; o >>= 1) {
                v0 += __shfl_xor_sync(0xFFFFFFFFu, v0, o);
                v1 += __shfl_xor_sync(0xFFFFFFFFu, v1, o);
                v2 += __shfl_xor_sync(0xFFFFFFFFu, v2, o);
                v3 += __shfl_xor_sync(0xFFFFFFFFu, v3, o);
            }
            float e0 = __expf(v0 * SCALE_INV);
            float e1 = __expf(v1 * SCALE_INV);
            float e2 = __expf(v2 * SCALE_INV);
            float e3 = __expf(v3 * SCALE_INV);
            den += (e0 + e1) + (e2 + e3);
            ax += e0*h0x + e1*h1x + e2*h2x + e3*h3x;
            ay += e0*h0y + e1*h1y + e2*h2y + e3*h3y;
            az += e0*h0z + e1*h1z + e2*h2z + e3*h3z;
            aw += e0*h0w + e1*h1w + e2*h2w + e3*h3w;
        }
        for (; j < m; j++) {
            unsigned o0 = (unsigned)__shfl_sync(0xFFFFFFFFu, myS, j) * 256u + lo;
            float kx,ky,kz,kw, hx,hy,hz,hw;
            load_kh(o0, kx,ky,kz,kw, hx,hy,hz,hw);
            float v0 = q.x*kx + q.y*ky + q.z*kz + q.w*kw;
#pragma unroll
            for (int o = 16; o > 0; o >>= 1)
                v0 += __shfl_xor_sync(0xFFFFFFFFu, v0, o);
            float e0 = __expf(v0 * SCALE_INV);
            den += e0;
            ax += e0*hx; ay += e0*hy; az += e0*hz; aw += e0*hw;
        }
    }

    float inv = 1.0f / den;
    *(float4*)orow = make_float4(ax * inv, ay * inv, az * inv, aw * inv);
}

// ---------------------------------------------------------------------------
// Inputs: 0 feat, 1 loc, 2 W_fc, 3 Wq, 4 Wk, 5 Wq2, 6 Wk2, 7 G_w, 8 embed,
// 9 boundaries, 10 src, 11 dst, 12 inter_ids  (e2 branch is dead code)
// ---------------------------------------------------------------------------
extern "C" void kernel_launch(void* const* d_in, const int* in_sizes, int n_in,
                              void* d_out, int out_size)
{
    const float* feat = (const float*)d_in[0];
    const float* Wfc  = (const float*)d_in[2];
    const float* Wq   = (const float*)d_in[3];
    const float* Wk   = (const float*)d_in[4];
    const int*   src  = (const int*)d_in[10];
    const int*   dst  = (const int*)d_in[11];
    float* out = (float*)d_out;

    static cudaStream_t s2 = nullptr;
    static cudaEvent_t evFork = nullptr, evJoin = nullptr;
    if (!s2) {
        cudaFuncSetAttribute(gemm3_tf32_kernel,
                             cudaFuncAttributeMaxDynamicSharedMemorySize,
                             SMEM_BYTES);
        cudaStreamCreateWithFlags(&s2, cudaStreamNonBlocking);
        cudaEventCreateWithFlags(&evFork, cudaEventDisableTiming);
        cudaEventCreateWithFlags(&evJoin, cudaEventDisableTiming);
    }

    // fork: CSR build on s2, GEMM on the main (capture) stream
    cudaEventRecord(evFork, 0);
    cudaStreamWaitEvent(s2, evFork, 0);

    {   // --- s2: CSR build ---
        int t8 = (N_EDGES + 7) / 8;
        hist_kernel<<<(t8 + 255) / 256, 256, 0, s2>>>(dst);
        scan1_kernel<<<NBLK, 256, 0, s2>>>();
        scan23_kernel<<<NBLK, 256, 0, s2>>>();
        scatter_kernel<<<(t8 + 255) / 256, 256, 0, s2>>>(src, dst);
        cudaEventRecord(evJoin, s2);
    }

    // --- main stream: H, Q, K GEMMs ---
    gemm3_tf32_kernel<<<(N_NODES + 127) / 128, 256, SMEM_BYTES>>>(
        feat, Wfc, Wq, Wk);

    // join, then fused attention
    cudaStreamWaitEvent(0, evJoin, 0);
    fused_attn_kernel<<<(N_NODES * 32 + 255) / 256, 256>>>(out);
}

// round 9
// speedup vs baseline: 2.6072x; 1.0170x over previous
#include <cuda_runtime.h>
#include <cuda_fp16.h>
#include <cstdint>

#define N_NODES 40000
#define N_EDGES 640000
#define F 128
#define SCALE_INV 0.08838834764831845f   // 1/sqrt(128)

#define NBLK 157            // ceil(40000/256) scan blocks

#define LDA 132
#define LDB 136
#define SMEM_BYTES ((128 * LDA + 128 * LDB) * 4)   // 137216 B

// ---- static scratch ----
// Interleaved K/H (fp16): per node, 32 groups of 8 halves (512 B per node):
//   [g*8+0..3] = K cols 4g..4g+3,  [g*8+4..7] = H cols 4g..4g+3
__device__ __half g_KH[N_NODES * 2 * F];
__device__ float  g_Q [N_NODES * F];     // (feat @ Wq) * (1/sqrt(F))  fp32
__device__ int    g_deg[N_NODES];        // stays zero between invocations
__device__ int    g_rowStart[N_NODES + 1];
__device__ int    g_cursor[N_NODES];
__device__ int    g_srcOff[N_EDGES];     // src node id << 9 (BYTE offset in g_KH)
__device__ int    g_bsum[NBLK];

// ---------------------------------------------------------------------------
__global__ void hist_kernel(const int* __restrict__ dst) {
    int base = (blockIdx.x * blockDim.x + threadIdx.x) << 2;   // 4 edges/thread
    if (base + 3 < N_EDGES) {
        int4 d = *(const int4*)(dst + base);
        atomicAdd(&g_deg[d.x], 1); atomicAdd(&g_deg[d.y], 1);
        atomicAdd(&g_deg[d.z], 1); atomicAdd(&g_deg[d.w], 1);
    } else {
        for (int e = base; e < N_EDGES; e++)
            atomicAdd(&g_deg[__ldg(&dst[e])], 1);
    }
}

// block-local exclusive scan of deg -> rowStart(local), block totals -> bsum.
// Zeroes g_deg after reading (invariant for next invocation).
__global__ __launch_bounds__(256) void scan1_kernel() {
    __shared__ int s[256];
    int tid = threadIdx.x;
    int i = blockIdx.x * 256 + tid;
    int v = 0;
    if (i < N_NODES) { v = g_deg[i]; g_deg[i] = 0; }
    s[tid] = v;
    __syncthreads();
#pragma unroll
    for (int off = 1; off < 256; off <<= 1) {
        int t = (tid >= off) ? s[tid - off] : 0;
        __syncthreads();
        s[tid] += t;
        __syncthreads();
    }
    if (i < N_NODES) g_rowStart[i] = s[tid] - v;
    if (tid == 255) g_bsum[blockIdx.x] = s[255];
}

// add block offsets (each block reduces bsum[t < blockIdx] itself);
// copy to cursor; set sentinel.
__global__ __launch_bounds__(256) void scan23_kernel() {
    __shared__ int red[256];
    int tid = threadIdx.x;
    int v = (tid < NBLK && tid < blockIdx.x) ? g_bsum[tid] : 0;
    red[tid] = v;
    __syncthreads();
#pragma unroll
    for (int off = 128; off > 0; off >>= 1) {
        if (tid < off) red[tid] += red[tid + off];
        __syncthreads();
    }
    int offset = red[0];

    int i = blockIdx.x * 256 + tid;
    if (i < N_NODES) {
        int r = g_rowStart[i] + offset;
        g_rowStart[i] = r;
        g_cursor[i] = r;
    }
    if (i == 0) g_rowStart[N_NODES] = N_EDGES;
}

__global__ void scatter_kernel(const int* __restrict__ src,
                               const int* __restrict__ dst) {
    int base = (blockIdx.x * blockDim.x + threadIdx.x) << 2;   // 4 edges/thread
    if (base + 3 < N_EDGES) {
        int4 d = *(const int4*)(dst + base);
        int4 s = *(const int4*)(src + base);
        int a0 = atomicAdd(&g_cursor[d.x], 1);
        int a1 = atomicAdd(&g_cursor[d.y], 1);
        int a2 = atomicAdd(&g_cursor[d.z], 1);
        int a3 = atomicAdd(&g_cursor[d.w], 1);
        g_srcOff[a0] = s.x << 9; g_srcOff[a1] = s.y << 9;
        g_srcOff[a2] = s.z << 9; g_srcOff[a3] = s.w << 9;
    } else {
        for (int e = base; e < N_EDGES; e++) {
            int d = __ldg(&dst[e]);
            g_srcOff[atomicAdd(&g_cursor[d], 1)] = __ldg(&src[e]) << 9;
        }
    }
}

// ---------------------------------------------------------------------------
__device__ __forceinline__ uint32_t f2tf32(float x) {
    uint32_t r;
    asm("cvt.rna.tf32.f32 %0, %1;" : "=r"(r) : "f"(x));
    return r;
}

// Fused 3-way GEMM (tf32 tensor cores): one 128x128 row tile per CTA;
// A staged ONCE, the three weights staged sequentially into Bs.
// H (j=0) and K (j=2) write fp16 into the interleaved g_KH; Q (j=1) fp32,
// pre-scaled by 1/sqrt(F).
__global__ __launch_bounds__(256) void gemm3_tf32_kernel(
    const float* __restrict__ feat,
    const float* __restrict__ Wfc,
    const float* __restrict__ Wq,
    const float* __restrict__ Wk)
{
    extern __shared__ float sm[];
    float* As = sm;                 // [128][LDA]
    float* Bs = sm + 128 * LDA;     // [128][LDB]

    const int tid  = threadIdx.x;
    const int row0 = blockIdx.x * 128;

    for (int i = tid; i < 4096; i += 256) {
        int r = i >> 5, c4 = (i & 31) << 2;
        float4 v = make_float4(0.f, 0.f, 0.f, 0.f);
        if (row0 + r < N_NODES)
            v = *(const float4*)(feat + (size_t)(row0 + r) * F + c4);
        *(float4*)(As + r * LDA + c4) = v;
    }

    const int wid  = tid >> 5;
    const int lane = tid & 31;
    const int wm   = (wid & 3) << 5;
    const int wn   = (wid >> 2) << 6;
    const int grp  = lane >> 2;
    const int qid  = lane & 3;

    const float* Ws[3] = { Wfc, Wq, Wk };

#pragma unroll
    for (int j = 0; j < 3; j++) {
        __syncthreads();
        const float* W = Ws[j];
        for (int i = tid; i < 4096; i += 256) {
            int r = i >> 5, c4 = (i & 31) << 2;
            *(float4*)(Bs + r * LDB + c4) = *(const float4*)(W + r * F + c4);
        }
        __syncthreads();

        float acc[2][8][4];
#pragma unroll
        for (int mi = 0; mi < 2; mi++)
#pragma unroll
            for (int nt = 0; nt < 8; nt++)
#pragma unroll
                for (int c = 0; c < 4; c++) acc[mi][nt][c] = 0.0f;

#pragma unroll
        for (int ks = 0; ks < 16; ks++) {
            const int k0 = ks << 3;
            uint32_t a[2][4];
#pragma unroll
            for (int mi = 0; mi < 2; mi++) {
                const int rb = wm + (mi << 4);
                a[mi][0] = f2tf32(As[(rb + grp)     * LDA + k0 + qid]);
                a[mi][1] = f2tf32(As[(rb + grp + 8) * LDA + k0 + qid]);
                a[mi][2] = f2tf32(As[(rb + grp)     * LDA + k0 + qid + 4]);
                a[mi][3] = f2tf32(As[(rb + grp + 8) * LDA + k0 + qid + 4]);
            }
#pragma unroll
            for (int nt = 0; nt < 8; nt++) {
                const int n0 = wn + (nt << 3);
                uint32_t b0 = f2tf32(Bs[(k0 + qid)     * LDB + n0 + grp]);
                uint32_t b1 = f2tf32(Bs[(k0 + qid + 4) * LDB + n0 + grp]);
#pragma unroll
                for (int mi = 0; mi < 2; mi++) {
                    asm volatile(
                        "mma.sync.aligned.m16n8k8.row.col.f32.tf32.tf32.f32 "
                        "{%0,%1,%2,%3}, {%4,%5,%6,%7}, {%8,%9}, {%0,%1,%2,%3};"
                        : "+f"(acc[mi][nt][0]), "+f"(acc[mi][nt][1]),
                          "+f"(acc[mi][nt][2]), "+f"(acc[mi][nt][3])
                        : "r"(a[mi][0]), "r"(a[mi][1]), "r"(a[mi][2]),
                          "r"(a[mi][3]), "r"(b0), "r"(b1));
                }
            }
        }

        const int khOff = (j == 0) ? 4 : 0;   // H -> slot+4, K -> slot+0
#pragma unroll
        for (int mi = 0; mi < 2; mi++) {
            const int r = row0 + wm + (mi << 4) + grp;
#pragma unroll
            for (int nt = 0; nt < 8; nt++) {
                const int col = wn + (nt << 3) + (qid << 1);   // col even
                if (j == 1) {          // Q fp32, pre-scaled
                    if (r < N_NODES)
                        *(float2*)(g_Q + (size_t)r * F + col) =
                            make_float2(acc[mi][nt][0] * SCALE_INV,
                                        acc[mi][nt][1] * SCALE_INV);
                    if (r + 8 < N_NODES)
                        *(float2*)(g_Q + (size_t)(r + 8) * F + col) =
                            make_float2(acc[mi][nt][2] * SCALE_INV,
                                        acc[mi][nt][3] * SCALE_INV);
                } else {               // H/K fp16 interleaved
                    const int slot = ((col >> 2) << 3) + khOff + (col & 3);
                    if (r < N_NODES)
                        *(__half2*)(g_KH + (size_t)r * 256 + slot) =
                            __floats2half2_rn(acc[mi][nt][0], acc[mi][nt][1]);
                    if (r + 8 < N_NODES)
                        *(__half2*)(g_KH + (size_t)(r + 8) * 256 + slot) =
                            __floats2half2_rn(acc[mi][nt][2], acc[mi][nt][3]);
                }
            }
        }
    }
}

// ---------------------------------------------------------------------------
// Fused attention: one warp per dst node, ILP-4 batches with partitioned
// warp reduction — ONE exp per lane per 4-edge batch (4x fewer MUFU ops).
// Reduction tree (xor 16,8 then 4,2,1) is bitwise identical to the full
// butterfly.
// ---------------------------------------------------------------------------
__device__ __forceinline__ void load_kh(unsigned off,
    float& kx, float& ky, float& kz, float& kw,
    float& hx, float& hy, float& hz, float& hw)
{
    uint4 raw = *(const uint4*)((const char*)g_KH + off);
    float2 f0 = __half22float2(*(__half2*)&raw.x);
    float2 f1 = __half22float2(*(__half2*)&raw.y);
    float2 f2 = __half22float2(*(__half2*)&raw.z);
    float2 f3 = __half22float2(*(__half2*)&raw.w);
    kx = f0.x; ky = f0.y; kz = f1.x; kw = f1.y;
    hx = f2.x; hy = f2.y; hz = f3.x; hw = f3.y;
}

__global__ __launch_bounds__(256) void fused_attn_kernel(float* __restrict__ out)
{
    int gw = (blockIdx.x * blockDim.x + threadIdx.x) >> 5;   // node id
    if (gw >= N_NODES) return;
    int lane = threadIdx.x & 31;

    int beg = g_rowStart[gw];
    int end = g_rowStart[gw + 1];

    float* orow = out + (size_t)gw * F + lane * 4;
    if (beg == end) {
        *(float4*)orow = make_float4(0.f, 0.f, 0.f, 0.f);
        return;
    }

    float4 q = *(const float4*)(g_Q + (unsigned)(gw * F + lane * 4));

    float ax = 0.f, ay = 0.f, az = 0.f, aw = 0.f;
    float den = 0.f;
    const unsigned lo = (unsigned)(lane << 4);   // byte offset within row (16 B/lane)
    const int g = lane >> 3;                     // lane group 0..3

    for (int chunk = beg; chunk < end; chunk += 32) {
        int idx = chunk + lane;
        int myO = (idx < end) ? __ldg(&g_srcOff[idx]) : 0;
        int m = end - chunk; if (m > 32) m = 32;

        int j = 0;
        for (; j + 4 <= m; j += 4) {
            unsigned o0 = (unsigned)__shfl_sync(0xFFFFFFFFu, myO, j)     + lo;
            unsigned o1 = (unsigned)__shfl_sync(0xFFFFFFFFu, myO, j + 1) + lo;
            unsigned o2 = (unsigned)__shfl_sync(0xFFFFFFFFu, myO, j + 2) + lo;
            unsigned o3 = (unsigned)__shfl_sync(0xFFFFFFFFu, myO, j + 3) + lo;
            float k0x,k0y,k0z,k0w, h0x,h0y,h0z,h0w;
            float k1x,k1y,k1z,k1w, h1x,h1y,h1z,h1w;
            float k2x,k2y,k2z,k2w, h2x,h2y,h2z,h2w;
            float k3x,k3y,k3z,k3w, h3x,h3y,h3z,h3w;
            load_kh(o0, k0x,k0y,k0z,k0w, h0x,h0y,h0z,h0w);
            load_kh(o1, k1x,k1y,k1z,k1w, h1x,h1y,h1z,h1w);
            load_kh(o2, k2x,k2y,k2z,k2w, h2x,h2y,h2z,h2w);
            load_kh(o3, k3x,k3y,k3z,k3w, h3x,h3y,h3z,h3w);

            float v0 = q.x*k0x + q.y*k0y + q.z*k0z + q.w*k0w;
            float v1 = q.x*k1x + q.y*k1y + q.z*k1z + q.w*k1w;
            float v2 = q.x*k2x + q.y*k2y + q.z*k2z + q.w*k2w;
            float v3 = q.x*k3x + q.y*k3y + q.z*k3z + q.w*k3w;

            // partitioned reduction: levels 16,8 on all four
            v0 += __shfl_xor_sync(0xFFFFFFFFu, v0, 16);
            v1 += __shfl_xor_sync(0xFFFFFFFFu, v1, 16);
            v2 += __shfl_xor_sync(0xFFFFFFFFu, v2, 16);
            v3 += __shfl_xor_sync(0xFFFFFFFFu, v3, 16);
            v0 += __shfl_xor_sync(0xFFFFFFFFu, v0, 8);
            v1 += __shfl_xor_sync(0xFFFFFFFFu, v1, 8);
            v2 += __shfl_xor_sync(0xFFFFFFFFu, v2, 8);
            v3 += __shfl_xor_sync(0xFFFFFFFFu, v3, 8);
            // each 8-lane group takes one edge's partial (xor 4,2,1 stay in-group)
            float x = v0;
            x = (g == 1) ? v1 : x;
            x = (g == 2) ? v2 : x;
            x = (g == 3) ? v3 : x;
            x += __shfl_xor_sync(0xFFFFFFFFu, x, 4);
            x += __shfl_xor_sync(0xFFFFFFFFu, x, 2);
            x += __shfl_xor_sync(0xFFFFFFFFu, x, 1);
            float y = __expf(x);                     // ONE exp per lane
            float e0 = __shfl_sync(0xFFFFFFFFu, y, 0);
            float e1 = __shfl_sync(0xFFFFFFFFu, y, 8);
            float e2 = __shfl_sync(0xFFFFFFFFu, y, 16);
            float e3 = __shfl_sync(0xFFFFFFFFu, y, 24);

            den += (e0 + e1) + (e2 + e3);
            ax += e0*h0x + e1*h1x + e2*h2x + e3*h3x;
            ay += e0*h0y + e1*h1y + e2*h2y + e3*h3y;
            az += e0*h0z + e1*h1z + e2*h2z + e3*h3z;
            aw += e0*h0w + e1*h1w + e2*h2w + e3*h3w;
        }
        for (; j < m; j++) {
            unsigned o0 = (unsigned)__shfl_sync(0xFFFFFFFFu, myO, j) + lo;
            float kx,ky,kz,kw, hx,hy,hz,hw;
            load_kh(o0, kx,ky,kz,kw, hx,hy,hz,hw);
            float v0 = q.x*kx + q.y*ky + q.z*kz + q.w*kw;
#pragma unroll
            for (int o = 16; o > 0; o >>= 1)
                v0 += __shfl_xor_sync(0xFFFFFFFFu, v0, o);
            float e0 = __expf(v0);
            den += e0;
            ax += e0*hx; ay += e0*hy; az += e0*hz; aw += e0*hw;
        }
    }

    float inv = 1.0f / den;
    *(float4*)orow = make_float4(ax * inv, ay * inv, az * inv, aw * inv);
}

// ---------------------------------------------------------------------------
// Inputs: 0 feat, 1 loc, 2 W_fc, 3 Wq, 4 Wk, 5 Wq2, 6 Wk2, 7 G_w, 8 embed,
// 9 boundaries, 10 src, 11 dst, 12 inter_ids  (e2 branch is dead code)
// ---------------------------------------------------------------------------
extern "C" void kernel_launch(void* const* d_in, const int* in_sizes, int n_in,
                              void* d_out, int out_size)
{
    const float* feat = (const float*)d_in[0];
    const float* Wfc  = (const float*)d_in[2];
    const float* Wq   = (const float*)d_in[3];
    const float* Wk   = (const float*)d_in[4];
    const int*   src  = (const int*)d_in[10];
    const int*   dst  = (const int*)d_in[11];
    float* out = (float*)d_out;

    static cudaStream_t s2 = nullptr;
    static cudaEvent_t evFork = nullptr, evJoin = nullptr;
    if (!s2) {
        cudaFuncSetAttribute(gemm3_tf32_kernel,
                             cudaFuncAttributeMaxDynamicSharedMemorySize,
                             SMEM_BYTES);
        cudaStreamCreateWithFlags(&s2, cudaStreamNonBlocking);
        cudaEventCreateWithFlags(&evFork, cudaEventDisableTiming);
        cudaEventCreateWithFlags(&evJoin, cudaEventDisableTiming);
    }

    // fork: CSR build on s2, GEMM on the main (capture) stream
    cudaEventRecord(evFork, 0);
    cudaStreamWaitEvent(s2, evFork, 0);

    {   // --- s2: CSR build ---
        int t4 = (N_EDGES + 3) / 4;
        hist_kernel<<<(t4 + 255) / 256, 256, 0, s2>>>(dst);
        scan1_kernel<<<NBLK, 256, 0, s2>>>();
        scan23_kernel<<<NBLK, 256, 0, s2>>>();
        scatter_kernel<<<(t4 + 255) / 256, 256, 0, s2>>>(src, dst);
        cudaEventRecord(evJoin, s2);
    }

    // --- main stream: H, Q, K GEMMs ---
    gemm3_tf32_kernel<<<(N_NODES + 127) / 128, 256, SMEM_BYTES>>>(
        feat, Wfc, Wq, Wk);

    // join, then fused attention
    cudaStreamWaitEvent(0, evJoin, 0);
    fused_attn_kernel<<<(N_NODES * 32 + 255) / 256, 256>>>(out);
}